// round 1
// baseline (speedup 1.0000x reference)
#include <cuda_runtime.h>
#include <cuda_bf16.h>

// 3x3 median filter, zero padding, exact median (lower median of 9 = true median).
// x: (32, 3, 512, 512) fp32 -> treated as N=96 images of 512x512.
//
// Each thread computes 4 horizontally-consecutive outputs (one float4 store).
// Algorithm: sort each vertical 3-column once (shared across adjacent outputs),
// then median9 = med3( max3(lows), med3(mids), min3(highs) )  [exact].

#define W 512
#define H 512
#define NIMG 96

__device__ __forceinline__ void sort3(float& a, float& b, float& c) {
    float t;
    t = fminf(a, b); b = fmaxf(a, b); a = t;
    t = fminf(b, c); c = fmaxf(b, c); b = t;
    t = fminf(a, b); b = fmaxf(a, b); a = t;
}

__device__ __forceinline__ float med3(float a, float b, float c) {
    return fmaxf(fminf(a, b), fminf(fmaxf(a, b), c));
}

__device__ __forceinline__ float max3(float a, float b, float c) {
    return fmaxf(fmaxf(a, b), c);
}

__device__ __forceinline__ float min3(float a, float b, float c) {
    return fminf(fminf(a, b), c);
}

__global__ void __launch_bounds__(256)
median3x3_kernel(const float* __restrict__ x, float* __restrict__ out) {
    // One thread = 4 output pixels (one float4), row-major over N*H rows.
    const int tid = blockIdx.x * blockDim.x + threadIdx.x;
    const int lanes_per_row = W / 4;               // 128
    const int row_id = tid >> 7;                   // tid / 128
    const int cb = (tid & 127) << 2;               // column base, multiple of 4
    if (row_id >= NIMG * H) return;

    const int y = row_id & (H - 1);
    const float* img = x + ((size_t)(row_id - y)) * W;   // n*H*W

    // Load 3 rows x 6 columns (cb-1 .. cb+4). Zero-pad out of bounds.
    float r0[6], r1[6], r2[6];

    #pragma unroll
    for (int dy = 0; dy < 3; dy++) {
        float* dst = (dy == 0) ? r0 : (dy == 1) ? r1 : r2;
        const int yy = y + dy - 1;
        if (yy >= 0 && yy < H) {
            const float* rowp = img + yy * W;
            const float4 v = *reinterpret_cast<const float4*>(rowp + cb);
            dst[0] = (cb > 0)       ? __ldg(rowp + cb - 1) : 0.0f;
            dst[1] = v.x; dst[2] = v.y; dst[3] = v.z; dst[4] = v.w;
            dst[5] = (cb + 4 < W)   ? __ldg(rowp + cb + 4) : 0.0f;
        } else {
            #pragma unroll
            for (int i = 0; i < 6; i++) dst[i] = 0.0f;
        }
    }

    // Sort the 6 vertical triples: after sort3, r0=lo, r1=mid, r2=hi.
    #pragma unroll
    for (int i = 0; i < 6; i++) sort3(r0[i], r1[i], r2[i]);

    // 4 outputs: window over columns (j, j+1, j+2)
    float o[4];
    #pragma unroll
    for (int j = 0; j < 4; j++) {
        const float lo = max3(r0[j], r0[j + 1], r0[j + 2]);
        const float mi = med3(r1[j], r1[j + 1], r1[j + 2]);
        const float hi = min3(r2[j], r2[j + 1], r2[j + 2]);
        o[j] = med3(lo, mi, hi);
    }

    float4 res;
    res.x = o[0]; res.y = o[1]; res.z = o[2]; res.w = o[3];
    reinterpret_cast<float4*>(out)[tid] = res;
}

extern "C" void kernel_launch(void* const* d_in, const int* in_sizes, int n_in,
                              void* d_out, int out_size) {
    const float* x = (const float*)d_in[0];
    float* out = (float*)d_out;

    const int total_threads = (NIMG * H * W) / 4;   // 6,291,456
    const int block = 256;
    const int grid = (total_threads + block - 1) / block;
    median3x3_kernel<<<grid, block>>>(x, out);
}

// round 2
// speedup vs baseline: 1.0088x; 1.0088x over previous
#include <cuda_runtime.h>
#include <cuda_bf16.h>

// 3x3 median filter, zero padding, exact median of 9.
// x: (32, 3, 512, 512) fp32 -> 96 images of 512x512.
//
// Each thread: 8 horizontally-consecutive outputs (two float4 stores).
// Column triples sorted once (shared across 3 horizontal windows), then
// sliding-window combines share sort2 pairs between adjacent windows by
// alternating med3/max3 formulations. ~17.5 FMNMX/pixel.

#define W 512
#define H 512
#define NIMG 96

__device__ __forceinline__ void sort3(float& a, float& b, float& c) {
    float t;
    t = fminf(a, b); b = fmaxf(a, b); a = t;
    t = fminf(b, c); c = fmaxf(b, c); b = t;
    t = fminf(a, b); b = fmaxf(a, b); a = t;
}

__device__ __forceinline__ float med3(float a, float b, float c) {
    // median{a,b,c}
    return fmaxf(fminf(a, b), fminf(fmaxf(a, b), c));
}

__global__ void __launch_bounds__(256)
median3x3_kernel(const float* __restrict__ x, float* __restrict__ out) {
    // One thread = 8 output pixels. 64 threads per image row.
    const int tid = blockIdx.x * blockDim.x + threadIdx.x;
    const int row_id = tid >> 6;                  // tid / 64
    const int cb = (tid & 63) << 3;               // column base, multiple of 8

    const int y = row_id & (H - 1);
    const float* img = x + ((size_t)(row_id - y)) * W;   // image base (n*H*W)

    // Load 3 rows x 10 columns (cb-1 .. cb+8). Zero-pad out of bounds.
    float r0[10], r1[10], r2[10];

    #pragma unroll
    for (int dy = 0; dy < 3; dy++) {
        float* dst = (dy == 0) ? r0 : (dy == 1) ? r1 : r2;
        const int yy = y + dy - 1;
        if (yy >= 0 && yy < H) {
            const float* rowp = img + yy * W;
            const float4 v0 = *reinterpret_cast<const float4*>(rowp + cb);
            const float4 v1 = *reinterpret_cast<const float4*>(rowp + cb + 4);
            dst[0] = (cb > 0)     ? __ldg(rowp + cb - 1) : 0.0f;
            dst[1] = v0.x; dst[2] = v0.y; dst[3] = v0.z; dst[4] = v0.w;
            dst[5] = v1.x; dst[6] = v1.y; dst[7] = v1.z; dst[8] = v1.w;
            dst[9] = (cb + 8 < W) ? __ldg(rowp + cb + 8) : 0.0f;
        } else {
            #pragma unroll
            for (int i = 0; i < 10; i++) dst[i] = 0.0f;
        }
    }

    // Sort the 10 vertical triples: r0=lo, r1=mid, r2=hi.
    #pragma unroll
    for (int i = 0; i < 10; i++) sort3(r0[i], r1[i], r2[i]);

    // ---- max3 over lows, sliding windows j..j+2, shared odd pairs ----
    // pairmax A_i = max(lo_i, lo_{i+1}) for i = 1,3,5,7; each serves 2 windows.
    float winlo[8], winhi[8], winmi[8];
    #pragma unroll
    for (int t = 0; t < 4; t++) {
        const int i = 2 * t + 1;
        const float A = fmaxf(r0[i], r0[i + 1]);
        winlo[2 * t]     = fmaxf(A, r0[2 * t]);      // window 2t: cols 2t..2t+2
        winlo[2 * t + 1] = fmaxf(A, r0[2 * t + 3]);  // window 2t+1: cols 2t+1..2t+3
    }

    // ---- min3 over highs, same sharing ----
    #pragma unroll
    for (int t = 0; t < 4; t++) {
        const int i = 2 * t + 1;
        const float B = fminf(r2[i], r2[i + 1]);
        winhi[2 * t]     = fminf(B, r2[2 * t]);
        winhi[2 * t + 1] = fminf(B, r2[2 * t + 3]);
    }

    // ---- med3 over mids: sort2 pair (2t+1, 2t+2) serves windows 2t and 2t+1 ----
    // window 2t  (cols 2t..2t+2),  pair after : med = max(mn, min(mx, m_{2t}))
    // window 2t+1(cols 2t+1..2t+3), pair before: med = min(mx, max(mn, m_{2t+3}))
    #pragma unroll
    for (int t = 0; t < 4; t++) {
        const int i = 2 * t + 1;
        const float mn = fminf(r1[i], r1[i + 1]);
        const float mx = fmaxf(r1[i], r1[i + 1]);
        winmi[2 * t]     = fmaxf(mn, fminf(mx, r1[2 * t]));
        winmi[2 * t + 1] = fminf(mx, fmaxf(mn, r1[2 * t + 3]));
    }

    // ---- final: median9 = med3(max3(lows), med3(mids), min3(highs)) ----
    float o[8];
    #pragma unroll
    for (int j = 0; j < 8; j++)
        o[j] = med3(winlo[j], winmi[j], winhi[j]);

    float4 a, b;
    a.x = o[0]; a.y = o[1]; a.z = o[2]; a.w = o[3];
    b.x = o[4]; b.y = o[5]; b.z = o[6]; b.w = o[7];
    float4* op = reinterpret_cast<float4*>(out + (size_t)row_id * W + cb);
    op[0] = a;
    op[1] = b;
}

extern "C" void kernel_launch(void* const* d_in, const int* in_sizes, int n_in,
                              void* d_out, int out_size) {
    const float* x = (const float*)d_in[0];
    float* out = (float*)d_out;

    const int total_threads = (NIMG * H * W) / 8;   // 3,145,728
    const int block = 256;
    const int grid = total_threads / block;          // 12288
    median3x3_kernel<<<grid, block>>>(x, out);
}